// round 10
// baseline (speedup 1.0000x reference)
#include <cuda_runtime.h>
#include <cuda.h>
#include <cuda_bf16.h>
#include <cstdint>

// 8x8 DCT-II coefficients, 0.5*cos(pi*(2m+1)k/16) pre-folded (orthonormal).
#define K0 0.3535533905932738f   // 1/(2*sqrt(2))
#define K1 0.4903926402016152f
#define K2 0.4619397662556434f
#define K3 0.4157348061512726f
#define K5 0.2777851165098011f
#define K6 0.1913417161825449f
#define K7 0.0975451610080642f

// SW128 swizzle (Swizzle<3,4,3>): XOR bits[6:4] with bits[9:7].
#define SWZ(o) ((o) ^ (((o) >> 3) & 0x70))

// In-place 8-point DCT-II (orthonormal), butterfly (even/odd) form.
__device__ __forceinline__ void dct8(float* v) {
    float s0 = v[0] + v[7], s1 = v[1] + v[6], s2 = v[2] + v[5], s3 = v[3] + v[4];
    float d0 = v[0] - v[7], d1 = v[1] - v[6], d2 = v[2] - v[5], d3 = v[3] - v[4];
    float e0 = s0 + s3, e1 = s1 + s2;
    float o0 = s0 - s3, o1 = s1 - s2;
    v[0] = K0 * (e0 + e1);
    v[4] = K0 * (e0 - e1);
    v[2] = K2 * o0 + K6 * o1;
    v[6] = K6 * o0 - K2 * o1;
    v[1] = K1 * d0 + K3 * d1 + K5 * d2 + K7 * d3;
    v[3] = K3 * d0 - K7 * d1 - K1 * d2 - K5 * d3;
    v[5] = K5 * d0 - K1 * d1 + K7 * d2 + K3 * d3;
    v[7] = K7 * d0 - K5 * d1 + K3 * d2 - K1 * d3;
}

// CTA = 64 rows x 32 cols of the (262144 x 128) fp32 image.
// TMA 8KB box in -> 8 warps each process an 8x32 tile (4 blocks) -> 8KB box out.
// Warp thread mapping (j = lane>>2, b = lane&3): row j of block b.
__global__ void __launch_bounds__(256)
dct_quant_tma_kernel(const __grid_constant__ CUtensorMap tmi,
                     const __grid_constant__ CUtensorMap tmo,
                     const float* __restrict__ q) {
    __shared__ alignas(1024) float sin_[2048];   // 8KB in-stage  (SW128 box)
    __shared__ alignas(1024) float sout[2048];   // 8KB out-stage (SW128 box)
    __shared__ float tr[8][4][8][9];             // per-warp transpose, pad 9
    __shared__ float srq[64];
    __shared__ alignas(8) unsigned long long mbar;

    const int tid  = threadIdx.x;
    const int wid  = tid >> 5;
    const int lane = tid & 31;
    const int j    = lane >> 2;   // row within block -> horizontal freq after transpose
    const int b    = lane & 3;    // block within warp tile

    const uint32_t mb = (uint32_t)__cvta_generic_to_shared(&mbar);
    const uint32_t si = (uint32_t)__cvta_generic_to_shared(sin_);
    const uint32_t so = (uint32_t)__cvta_generic_to_shared(sout);

    if (tid < 64) srq[tid] = 1.0f / q[tid];
    if (tid == 0) {
        asm volatile("mbarrier.init.shared.b64 [%0], %1;" :: "r"(mb), "r"(1u) : "memory");
    }
    __syncthreads();

    // CTA coords: 4096 vertical bands (64 rows) x 4 col-groups (32 floats)
    const int cx = (blockIdx.x & 3) << 5;
    const int cy = (blockIdx.x >> 2) << 6;

    if (tid == 0) {
        asm volatile("mbarrier.arrive.expect_tx.shared.b64 _, [%0], %1;"
                     :: "r"(mb), "r"(8192u) : "memory");
        asm volatile(
            "cp.async.bulk.tensor.2d.shared::cta.global.tile.mbarrier::complete_tx::bytes "
            "[%0], [%1, {%2, %3}], [%4];"
            :: "r"(si), "l"(&tmi), "r"(cx), "r"(cy), "r"(mb) : "memory");
    }

    // All threads wait for the TMA load (parity 0).
    {
        uint32_t done;
        asm volatile(
            "{\n\t.reg .pred p;\n\t"
            "mbarrier.try_wait.parity.acquire.cta.shared::cta.b64 p, [%1], %2;\n\t"
            "selp.b32 %0, 1, 0, p;\n\t}"
            : "=r"(done) : "r"(mb), "r"(0u) : "memory");
        if (!done) {
            asm volatile(
                "{\n\t.reg .pred P1;\n\t"
                "WL_%=:\n\t"
                "mbarrier.try_wait.parity.acquire.cta.shared::cta.b64 P1, [%0], %1, 0x989680;\n\t"
                "@P1 bra.uni WD_%=;\n\t"
                "bra.uni WL_%=;\n\t"
                "WD_%=:\n\t}"
                :: "r"(mb), "r"(0u) : "memory");
        }
    }

    // Read this thread's block-row from the swizzled in-stage: row wid*8+j,
    // bytes b*32 and b*32+16. Chunk-slot = (2b+h) ^ (j&7): conflict-free
    // per quarter-phase (each phase hits 8 distinct 16B slots).
    float r[8];
    {
        const char* sb = reinterpret_cast<const char*>(sin_);
        uint32_t base = (uint32_t)((wid * 8 + j) * 128 + b * 32);
        float4 lo = *reinterpret_cast<const float4*>(sb + SWZ(base));
        float4 hi = *reinterpret_cast<const float4*>(sb + SWZ(base + 16));
        r[0] = lo.x; r[1] = lo.y; r[2] = lo.z; r[3] = lo.w;
        r[4] = hi.x; r[5] = hi.y; r[6] = hi.z; r[7] = hi.w;
    }

    // Row pass
    dct8(r);

    // Per-warp padded-smem transpose (conflict-free both directions, as R5).
    float* ts = &tr[wid][b][0][0];
    #pragma unroll
    for (int c = 0; c < 8; c++) ts[c * 9 + j] = r[c];
    __syncwarp();
    #pragma unroll
    for (int i = 0; i < 8; i++) r[i] = ts[j * 9 + i];

    // Column pass
    dct8(r);

    // Quantize + round-half-even + clip; write to swizzled out-stage.
    // For fixed v: word lane-pattern covers all 32 banks (4-word chunks XORed
    // within a 128B row -> permutation of the row's 32 words).
    {
        char* ob = reinterpret_cast<char*>(sout);
        #pragma unroll
        for (int v = 0; v < 8; v++) {
            float y = rintf(r[v] * srq[v * 8 + j]);
            y = fminf(fmaxf(y, -128.0f), 127.0f);
            uint32_t boff = (uint32_t)((wid * 8 + v) * 128 + (b * 8 + j) * 4);
            *reinterpret_cast<float*>(ob + SWZ(boff)) = y;
        }
    }

    __syncthreads();

    if (tid == 0) {
        asm volatile("fence.proxy.async.shared::cta;" ::: "memory");
        asm volatile(
            "cp.async.bulk.tensor.2d.global.shared::cta.tile.bulk_group "
            "[%0, {%1, %2}], [%3];"
            :: "l"(&tmo), "r"(cx), "r"(cy), "r"(so) : "memory");
        asm volatile("cp.async.bulk.commit_group;" ::: "memory");
        asm volatile("cp.async.bulk.wait_group 0;" ::: "memory");
    }
}

// ---------------- host side ----------------

typedef CUresult (*PFN_encodeTiled)(
    CUtensorMap*, CUtensorMapDataType, cuuint32_t, void*,
    const cuuint64_t*, const cuuint64_t*, const cuuint32_t*, const cuuint32_t*,
    CUtensorMapInterleave, CUtensorMapSwizzle, CUtensorMapL2promotion,
    CUtensorMapFloatOOBfill);

static void encode_map(PFN_encodeTiled fn, CUtensorMap* tm, void* ptr) {
    cuuint64_t dims[2]    = {128, 262144};      // width (elems), height (rows)
    cuuint64_t strides[1] = {512};              // row stride in bytes
    cuuint32_t box[2]     = {32, 64};           // 128B x 64 rows = 8KB
    cuuint32_t estr[2]    = {1, 1};
    fn(tm, CU_TENSOR_MAP_DATA_TYPE_FLOAT32, 2, ptr,
       dims, strides, box, estr,
       CU_TENSOR_MAP_INTERLEAVE_NONE, CU_TENSOR_MAP_SWIZZLE_128B,
       CU_TENSOR_MAP_L2_PROMOTION_L2_128B, CU_TENSOR_MAP_FLOAT_OOB_FILL_NONE);
}

extern "C" void kernel_launch(void* const* d_in, const int* in_sizes, int n_in,
                              void* d_out, int out_size) {
    const float* x = (const float*)d_in[0];
    const float* q = (const float*)d_in[1];
    float* out = (float*)d_out;

    // Resolve cuTensorMapEncodeTiled through the runtime (no -lcuda needed).
    PFN_encodeTiled fn = nullptr;
    {
        void* p = nullptr;
        cudaDriverEntryPointQueryResult qr;
        cudaGetDriverEntryPointByVersion("cuTensorMapEncodeTiled", &p, 12050,
                                         cudaEnableDefault, &qr);
        fn = (PFN_encodeTiled)p;
    }

    CUtensorMap tmi, tmo;
    encode_map(fn, &tmi, (void*)x);
    encode_map(fn, &tmo, (void*)out);

    // 262144 rows / 64 rows-per-CTA * 4 col-groups = 16384 CTAs
    dct_quant_tma_kernel<<<16384, 256>>>(tmi, tmo, q);
}

// round 12
// speedup vs baseline: 1.1352x; 1.1352x over previous
#include <cuda_runtime.h>
#include <cuda.h>
#include <cuda_bf16.h>
#include <cstdint>

// 8x8 DCT-II coefficients, 0.5*cos(pi*(2m+1)k/16) pre-folded (orthonormal).
#define K0 0.3535533905932738f   // 1/(2*sqrt(2))
#define K1 0.4903926402016152f
#define K2 0.4619397662556434f
#define K3 0.4157348061512726f
#define K5 0.2777851165098011f
#define K6 0.1913417161825449f
#define K7 0.0975451610080642f

// SW128 swizzle (Swizzle<3,4,3>): XOR bits[6:4] with bits[9:7].
#define SWZ(o) ((o) ^ (((o) >> 3) & 0x70))

// In-place 8-point DCT-II (orthonormal), butterfly (even/odd) form.
__device__ __forceinline__ void dct8(float* v) {
    float s0 = v[0] + v[7], s1 = v[1] + v[6], s2 = v[2] + v[5], s3 = v[3] + v[4];
    float d0 = v[0] - v[7], d1 = v[1] - v[6], d2 = v[2] - v[5], d3 = v[3] - v[4];
    float e0 = s0 + s3, e1 = s1 + s2;
    float o0 = s0 - s3, o1 = s1 - s2;
    v[0] = K0 * (e0 + e1);
    v[4] = K0 * (e0 - e1);
    v[2] = K2 * o0 + K6 * o1;
    v[6] = K6 * o0 - K2 * o1;
    v[1] = K1 * d0 + K3 * d1 + K5 * d2 + K7 * d3;
    v[3] = K3 * d0 - K7 * d1 - K1 * d2 - K5 * d3;
    v[5] = K5 * d0 - K1 * d1 + K7 * d2 + K3 * d3;
    v[7] = K7 * d0 - K5 * d1 + K3 * d2 - K1 * d3;
}

// Warp = one 8x32 tile (4 adjacent 8x8 blocks). Each warp issues ITS OWN 1KB
// TMA load (32x8 box = one SW128 atom) gated by a warp-private mbarrier ->
// no CTA-wide serialization, zero global-load L1tex wavefronts.
// Compute thread mapping (j = lane>>2, b = lane&3): row j of block b.
// Stores: direct col-oriented streaming STG.32 (one full 128B line per op).
__global__ void __launch_bounds__(256)
dct_quant_tma_kernel(const __grid_constant__ CUtensorMap tmi,
                     const float* __restrict__ q,
                     float* __restrict__ out) {
    __shared__ alignas(1024) float sin_[2048];   // 8 x 1KB per-warp slices
    __shared__ float tr[8][4][8][9];             // per-warp transpose, pad 9
    __shared__ float srq[8][64];                 // per-warp 1/q
    __shared__ alignas(8) unsigned long long mbar[8];

    const int tid  = threadIdx.x;
    const int wid  = tid >> 5;
    const int lane = tid & 31;
    const int j    = lane >> 2;   // row within block -> horizontal freq index
    const int b    = lane & 3;    // block within warp tile

    const int w  = blockIdx.x * 8 + wid;      // global tile id (131072 total)
    const int cy = (w >> 2) * 8;              // first image row of tile
    const int cx = (w & 3) * 32;              // first image col of tile

    const uint32_t mb    = (uint32_t)__cvta_generic_to_shared(&mbar[wid]);
    const uint32_t slice = (uint32_t)__cvta_generic_to_shared(sin_) + wid * 1024;

    // Per-warp 1/q table (visibility via the __syncwarp below).
    srq[wid][lane]      = 1.0f / q[lane];
    srq[wid][lane + 32] = 1.0f / q[lane + 32];

    if (lane == 0) {
        asm volatile("mbarrier.init.shared.b64 [%0], %1;" :: "r"(mb), "r"(1u) : "memory");
    }
    __syncwarp();

    if (lane == 0) {
        asm volatile("mbarrier.arrive.expect_tx.shared.b64 _, [%0], %1;"
                     :: "r"(mb), "r"(1024u) : "memory");
        asm volatile(
            "cp.async.bulk.tensor.2d.shared::cta.global.tile.mbarrier::complete_tx::bytes "
            "[%0], [%1, {%2, %3}], [%4];"
            :: "r"(slice), "l"(&tmi), "r"(cx), "r"(cy), "r"(mb) : "memory");
    }

    // Warp-local wait for this warp's slice (parity 0).
    {
        uint32_t done;
        asm volatile(
            "{\n\t.reg .pred p;\n\t"
            "mbarrier.try_wait.parity.acquire.cta.shared::cta.b64 p, [%1], %2;\n\t"
            "selp.b32 %0, 1, 0, p;\n\t}"
            : "=r"(done) : "r"(mb), "r"(0u) : "memory");
        if (!done) {
            asm volatile(
                "{\n\t.reg .pred P1;\n\t"
                "WL_%=:\n\t"
                "mbarrier.try_wait.parity.acquire.cta.shared::cta.b64 P1, [%0], %1, 0x989680;\n\t"
                "@P1 bra.uni WD_%=;\n\t"
                "bra.uni WL_%=;\n\t"
                "WD_%=:\n\t}"
                :: "r"(mb), "r"(0u) : "memory");
        }
    }

    // Read block-row (j of block b) from the swizzled 1KB slice.
    // Slice offset wid*1024 leaves swizzle bits [9:7]=j untouched; conflict-free
    // per quarter-phase (validated for correctness+banks in the R9 kernel).
    float r[8];
    {
        const char* sb = reinterpret_cast<const char*>(sin_) + wid * 1024;
        uint32_t base = (uint32_t)(j * 128 + b * 32);
        float4 lo = *reinterpret_cast<const float4*>(sb + SWZ(base));
        float4 hi = *reinterpret_cast<const float4*>(sb + SWZ(base + 16));
        r[0] = lo.x; r[1] = lo.y; r[2] = lo.z; r[3] = lo.w;
        r[4] = hi.x; r[5] = hi.y; r[6] = hi.z; r[7] = hi.w;
    }

    // Row pass (along memory-contiguous dimension)
    dct8(r);

    // Per-warp padded-smem transpose (conflict-free both directions, as R5).
    float* ts = &tr[wid][b][0][0];
    #pragma unroll
    for (int c = 0; c < 8; c++) ts[c * 9 + j] = r[c];
    __syncwarp();
    #pragma unroll
    for (int i = 0; i < 8; i++) r[i] = ts[j * 9 + i];

    // Column pass: register index v = vertical freq, j = horizontal freq
    dct8(r);

    // Quantize + round-half-even + clip, direct col-oriented streaming stores.
    // For fixed v, the warp writes one contiguous, fully-consumed 128B line.
    const float* sq = srq[wid];
    float* obase = out + (long)cy * 128 + cx + b * 8 + j;
    #pragma unroll
    for (int v = 0; v < 8; v++) {
        float y = rintf(r[v] * sq[v * 8 + j]);
        y = fminf(fmaxf(y, -128.0f), 127.0f);
        __stcs(obase + v * 128, y);
    }
}

// ---------------- host side ----------------

typedef CUresult (*PFN_encodeTiled)(
    CUtensorMap*, CUtensorMapDataType, cuuint32_t, void*,
    const cuuint64_t*, const cuuint64_t*, const cuuint32_t*, const cuuint32_t*,
    CUtensorMapInterleave, CUtensorMapSwizzle, CUtensorMapL2promotion,
    CUtensorMapFloatOOBfill);

extern "C" void kernel_launch(void* const* d_in, const int* in_sizes, int n_in,
                              void* d_out, int out_size) {
    const float* x = (const float*)d_in[0];
    const float* q = (const float*)d_in[1];
    float* out = (float*)d_out;

    // Resolve cuTensorMapEncodeTiled through the runtime (no -lcuda needed).
    PFN_encodeTiled fn = nullptr;
    {
        void* p = nullptr;
        cudaDriverEntryPointQueryResult qr;
        cudaGetDriverEntryPointByVersion("cuTensorMapEncodeTiled", &p, 12050,
                                         cudaEnableDefault, &qr);
        fn = (PFN_encodeTiled)p;
    }

    CUtensorMap tmi;
    {
        cuuint64_t dims[2]    = {128, 262144};   // width (elems), height (rows)
        cuuint64_t strides[1] = {512};           // row stride in bytes
        cuuint32_t box[2]     = {32, 8};         // 128B x 8 rows = 1KB (one SW128 atom)
        cuuint32_t estr[2]    = {1, 1};
        fn(&tmi, CU_TENSOR_MAP_DATA_TYPE_FLOAT32, 2, (void*)x,
           dims, strides, box, estr,
           CU_TENSOR_MAP_INTERLEAVE_NONE, CU_TENSOR_MAP_SWIZZLE_128B,
           CU_TENSOR_MAP_L2_PROMOTION_L2_128B, CU_TENSOR_MAP_FLOAT_OOB_FILL_NONE);
    }

    // 131072 tiles / 8 warps per CTA = 16384 CTAs
    dct_quant_tma_kernel<<<16384, 256>>>(tmi, q, out);
}

// round 13
// speedup vs baseline: 1.1854x; 1.0442x over previous
#include <cuda_runtime.h>
#include <cuda.h>
#include <cuda_bf16.h>
#include <cstdint>

// 8x8 DCT-II coefficients, 0.5*cos(pi*(2m+1)k/16) pre-folded (orthonormal).
#define K0 0.3535533905932738f   // 1/(2*sqrt(2))
#define K1 0.4903926402016152f
#define K2 0.4619397662556434f
#define K3 0.4157348061512726f
#define K5 0.2777851165098011f
#define K6 0.1913417161825449f
#define K7 0.0975451610080642f

// SW128 swizzle (Swizzle<3,4,3>): XOR bits[6:4] with bits[9:7].
#define SWZ(o) ((o) ^ (((o) >> 3) & 0x70))

// In-place 8-point DCT-II (orthonormal), butterfly (even/odd) form.
__device__ __forceinline__ void dct8(float* v) {
    float s0 = v[0] + v[7], s1 = v[1] + v[6], s2 = v[2] + v[5], s3 = v[3] + v[4];
    float d0 = v[0] - v[7], d1 = v[1] - v[6], d2 = v[2] - v[5], d3 = v[3] - v[4];
    float e0 = s0 + s3, e1 = s1 + s2;
    float o0 = s0 - s3, o1 = s1 - s2;
    v[0] = K0 * (e0 + e1);
    v[4] = K0 * (e0 - e1);
    v[2] = K2 * o0 + K6 * o1;
    v[6] = K6 * o0 - K2 * o1;
    v[1] = K1 * d0 + K3 * d1 + K5 * d2 + K7 * d3;
    v[3] = K3 * d0 - K7 * d1 - K1 * d2 - K5 * d3;
    v[5] = K5 * d0 - K1 * d1 + K7 * d2 + K3 * d3;
    v[7] = K7 * d0 - K5 * d1 + K3 * d2 - K1 * d3;
}

// Warp = 16x32 region = two vertically-stacked 8x32 tiles, fetched by ONE
// 2KB TMA load (32x16 box, SW128) gated by a warp-private mbarrier.
// Amortizes mbarrier/TMA overhead over 2 tiles and doubles per-warp
// bytes-in-flight vs 1KB ops (R10), with zero global-load L1 wavefronts.
// Compute per tile (j = lane>>2, b = lane&3): row j of block b; swizzled
// LDS.128 -> row DCT -> padded-smem transpose -> col DCT -> quantize ->
// col-oriented streaming STG.32 (one full 128B line per instruction).
__global__ void __launch_bounds__(256)
dct_quant_tma_kernel(const __grid_constant__ CUtensorMap tmi,
                     const float* __restrict__ q,
                     float* __restrict__ out) {
    __shared__ alignas(1024) float sin_[8 * 512];  // 8 x 2KB per-warp slices
    __shared__ float tr[8][4][8][9];               // per-warp transpose, pad 9
    __shared__ float srq[8][64];                   // per-warp 1/q
    __shared__ alignas(8) unsigned long long mbar[8];

    const int tid  = threadIdx.x;
    const int wid  = tid >> 5;
    const int lane = tid & 31;
    const int j    = lane >> 2;   // row within block -> horizontal freq index
    const int b    = lane & 3;    // block within tile

    // warp id over 65536 16x32 regions: img(2048) x br2(8) x tc(4)
    const int w   = blockIdx.x * 8 + wid;
    const int img = w >> 5;
    const int rem = w & 31;
    const int br2 = rem >> 2;                  // 16-row band within plane
    const int tc  = rem & 3;                   // 32-float column group
    const int cy  = img * 128 + br2 * 16;      // global row of region
    const int cx  = tc * 32;                   // global col of region

    const uint32_t mb    = (uint32_t)__cvta_generic_to_shared(&mbar[wid]);
    const uint32_t slice = (uint32_t)__cvta_generic_to_shared(sin_) + wid * 2048;

    // Per-warp 1/q table (visibility via warp-uniform execution + syncwarp).
    srq[wid][lane]      = 1.0f / q[lane];
    srq[wid][lane + 32] = 1.0f / q[lane + 32];

    if (lane == 0) {
        asm volatile("mbarrier.init.shared.b64 [%0], %1;" :: "r"(mb), "r"(1u) : "memory");
    }
    __syncwarp();

    if (lane == 0) {
        asm volatile("mbarrier.arrive.expect_tx.shared.b64 _, [%0], %1;"
                     :: "r"(mb), "r"(2048u) : "memory");
        asm volatile(
            "cp.async.bulk.tensor.2d.shared::cta.global.tile.mbarrier::complete_tx::bytes "
            "[%0], [%1, {%2, %3}], [%4];"
            :: "r"(slice), "l"(&tmi), "r"(cx), "r"(cy), "r"(mb) : "memory");
    }

    // Warp-local wait for this warp's 2KB slice (parity 0).
    {
        uint32_t done;
        asm volatile(
            "{\n\t.reg .pred p;\n\t"
            "mbarrier.try_wait.parity.acquire.cta.shared::cta.b64 p, [%1], %2;\n\t"
            "selp.b32 %0, 1, 0, p;\n\t}"
            : "=r"(done) : "r"(mb), "r"(0u) : "memory");
        if (!done) {
            asm volatile(
                "{\n\t.reg .pred P1;\n\t"
                "WL_%=:\n\t"
                "mbarrier.try_wait.parity.acquire.cta.shared::cta.b64 P1, [%0], %1, 0x989680;\n\t"
                "@P1 bra.uni WD_%=;\n\t"
                "bra.uni WL_%=;\n\t"
                "WD_%=:\n\t}"
                :: "r"(mb), "r"(0u) : "memory");
        }
    }

    const float* sq = srq[wid];
    float* ts = &tr[wid][b][0][0];
    // Swizzled smem read offsets (SW128 atom = 1024B of 8 rows; tile B is the
    // second atom at +1024 with the identical internal pattern).
    const uint32_t base0 = SWZ((uint32_t)(j * 128 + b * 32));
    const uint32_t base1 = SWZ((uint32_t)(j * 128 + b * 32 + 16));
    const char* sb = reinterpret_cast<const char*>(sin_) + wid * 2048;

    #pragma unroll
    for (int t = 0; t < 2; t++) {
        // Read block-row (j of block b) from swizzled slice half t.
        float r[8];
        {
            float4 lo = *reinterpret_cast<const float4*>(sb + t * 1024 + base0);
            float4 hi = *reinterpret_cast<const float4*>(sb + t * 1024 + base1);
            r[0] = lo.x; r[1] = lo.y; r[2] = lo.z; r[3] = lo.w;
            r[4] = hi.x; r[5] = hi.y; r[6] = hi.z; r[7] = hi.w;
        }

        // Row pass
        dct8(r);

        // Per-warp padded-smem transpose (conflict-free both directions).
        #pragma unroll
        for (int c = 0; c < 8; c++) ts[c * 9 + j] = r[c];
        __syncwarp();
        #pragma unroll
        for (int i = 0; i < 8; i++) r[i] = ts[j * 9 + i];

        // Column pass
        dct8(r);

        // Quantize + round-half-even + clip; col-oriented streaming stores.
        // For fixed v, the warp writes one contiguous 128B line.
        float* obase = out + (long)(cy + t * 8) * 128 + cx + b * 8 + j;
        #pragma unroll
        for (int v = 0; v < 8; v++) {
            float y = rintf(r[v] * sq[v * 8 + j]);
            y = fminf(fmaxf(y, -128.0f), 127.0f);
            __stcs(obase + v * 128, y);
        }

        // Protect warp-shared tr buffer before tile B rewrites it.
        __syncwarp();
    }
}

// ---------------- host side ----------------

typedef CUresult (*PFN_encodeTiled)(
    CUtensorMap*, CUtensorMapDataType, cuuint32_t, void*,
    const cuuint64_t*, const cuuint64_t*, const cuuint32_t*, const cuuint32_t*,
    CUtensorMapInterleave, CUtensorMapSwizzle, CUtensorMapL2promotion,
    CUtensorMapFloatOOBfill);

extern "C" void kernel_launch(void* const* d_in, const int* in_sizes, int n_in,
                              void* d_out, int out_size) {
    const float* x = (const float*)d_in[0];
    const float* q = (const float*)d_in[1];
    float* out = (float*)d_out;

    // Resolve cuTensorMapEncodeTiled through the runtime (no -lcuda needed).
    PFN_encodeTiled fn = nullptr;
    {
        void* p = nullptr;
        cudaDriverEntryPointQueryResult qr;
        cudaGetDriverEntryPointByVersion("cuTensorMapEncodeTiled", &p, 12050,
                                         cudaEnableDefault, &qr);
        fn = (PFN_encodeTiled)p;
    }

    CUtensorMap tmi;
    {
        cuuint64_t dims[2]    = {128, 262144};   // width (elems), height (rows)
        cuuint64_t strides[1] = {512};           // row stride in bytes
        cuuint32_t box[2]     = {32, 16};        // 128B x 16 rows = 2KB (two SW128 atoms)
        cuuint32_t estr[2]    = {1, 1};
        fn(&tmi, CU_TENSOR_MAP_DATA_TYPE_FLOAT32, 2, (void*)x,
           dims, strides, box, estr,
           CU_TENSOR_MAP_INTERLEAVE_NONE, CU_TENSOR_MAP_SWIZZLE_128B,
           CU_TENSOR_MAP_L2_PROMOTION_L2_128B, CU_TENSOR_MAP_FLOAT_OOB_FILL_NONE);
    }

    // 65536 warp-regions / 8 warps per CTA = 8192 CTAs
    dct_quant_tma_kernel<<<8192, 256>>>(tmi, q, out);
}